// round 5
// baseline (speedup 1.0000x reference)
#include <cuda_runtime.h>

// Problem constants
#define B_  256
#define S_  2048
#define I_  128
#define J_  40    // LSTM_IN
#define G_  80    // 4*H
#define H_  20

typedef unsigned long long u64;

#define L2E 1.4426950408889634f   // log2(e)

// Scratch gx layout per (b,s): 80 floats, PRE-SCALED by log2e (gate g rows by 2*log2e):
//   float 2j   = gate i, row j      float 2j+1  = gate f, row j
//   float 40+2j = gate g, row j     float 41+2j = gate o, row j
__device__ __align__(256) float g_gx[(size_t)S_ * B_ * G_];

// ---------------- helpers ----------------
__device__ __forceinline__ u64 pk2(float lo, float hi) {
    u64 r;
    asm("mov.b64 %0, {%1, %2};" : "=l"(r) : "f"(lo), "f"(hi));
    return r;
}
__device__ __forceinline__ void upk2(u64 v, float& lo, float& hi) {
    asm("mov.b64 {%0, %1}, %2;" : "=f"(lo), "=f"(hi) : "l"(v));
}
__device__ __forceinline__ void fma2(u64& d, u64 a, u64 b) {
    asm("fma.rn.f32x2 %0, %1, %2, %0;" : "+l"(d) : "l"(a), "l"(b));
}
__device__ __forceinline__ float ex2f(float x) {
    float r;
    asm("ex2.approx.f32 %0, %1;" : "=f"(r) : "f"(x));
    return r;
}
__device__ __forceinline__ float rcpf(float x) {
    float r;
    asm("rcp.approx.f32 %0, %1;" : "=f"(r) : "f"(x));
    return r;
}

// ---------------- GEMM kernel ----------------
// gx = relu(feed@W1^T + b1) @ Wih^T + (bih+bhh), scaled by log2e (2*log2e for gate g),
// written pair-permuted, batch-major. 64-row tiles, 128 threads, 2 blocks/SM.

#define TILE_R 64

struct SmemG {
    float feed[TILE_R][I_ + 4];  // stride 132 words
    float x[TILE_R][J_ + 4];     // stride 44
    float w1[J_][I_ + 4];        // stride 132
    float wih[G_][J_ + 2];       // stride 42
    float b1v[J_];
    float b2v[G_];
};

__global__ __launch_bounds__(128, 2) void gemm_kernel(
    const float* __restrict__ feed, const float* __restrict__ W1,
    const float* __restrict__ b1, const float* __restrict__ Wih,
    const float* __restrict__ bih, const float* __restrict__ bhh)
{
    extern __shared__ char smem_raw[];
    SmemG& sm = *reinterpret_cast<SmemG*>(smem_raw);
    const int tid  = threadIdx.x;
    const int tile = blockIdx.x;           // 8192 tiles
    const int s    = tile >> 2;            // 4 tiles per timestep
    const int bb   = (tile & 3) * 64;      // batch base

    // --- stage weights/biases (gate scale folded into wih & b2v) ---
    for (int idx = tid; idx < J_ * I_; idx += 128)
        sm.w1[idx / I_][idx % I_] = W1[idx];
    for (int idx = tid; idx < G_ * J_; idx += 128) {
        int row = idx / J_;
        float sc = (row >= 40 && row < 60) ? (2.f * L2E) : L2E;
        sm.wih[row][idx % J_] = Wih[idx] * sc;
    }
    if (tid < J_) sm.b1v[tid] = b1[tid];
    if (tid < G_) {
        float sc = (tid >= 40 && tid < 60) ? (2.f * L2E) : L2E;
        sm.b2v[tid] = (bih[tid] + bhh[tid]) * sc;
    }

    // --- stage feed tile (float4, coalesced) ---
    for (int idx = tid; idx < TILE_R * (I_ / 4); idx += 128) {
        int r  = idx >> 5;
        int c4 = idx & 31;
        float4 v = *reinterpret_cast<const float4*>(
            feed + ((size_t)(bb + r) * S_ + s) * I_ + c4 * 4);
        *reinterpret_cast<float4*>(&sm.feed[r][c4 * 4]) = v;
    }
    __syncthreads();

    const int cg = tid & 7;   // 8 col groups
    const int rg = tid >> 3;  // 16 row groups; rows rg + 16q

    // --- phase 1: x[r][j], j0 = cg*5 ---
    {
        const int j0 = cg * 5;
        u64 acc[4][5];
#pragma unroll
        for (int q = 0; q < 4; q++)
#pragma unroll
            for (int p = 0; p < 5; p++) acc[q][p] = 0ull;

#pragma unroll 2
        for (int k4 = 0; k4 < I_ / 4; k4++) {
            const int k = k4 * 4;
            ulonglong2 fr[4], wj[5];
#pragma unroll
            for (int q = 0; q < 4; q++)
                fr[q] = *reinterpret_cast<const ulonglong2*>(&sm.feed[rg + 16 * q][k]);
#pragma unroll
            for (int p = 0; p < 5; p++)
                wj[p] = *reinterpret_cast<const ulonglong2*>(&sm.w1[j0 + p][k]);
#pragma unroll
            for (int q = 0; q < 4; q++)
#pragma unroll
                for (int p = 0; p < 5; p++) {
                    fma2(acc[q][p], fr[q].x, wj[p].x);
                    fma2(acc[q][p], fr[q].y, wj[p].y);
                }
        }
#pragma unroll
        for (int q = 0; q < 4; q++)
#pragma unroll
            for (int p = 0; p < 5; p++) {
                float lo, hi;
                upk2(acc[q][p], lo, hi);
                float v = lo + hi + sm.b1v[j0 + p];
                sm.x[rg + 16 * q][j0 + p] = fmaxf(v, 0.f);
            }
    }
    __syncthreads();

    // --- phase 2: cg<4 -> (i,f) pairs for j in [5cg,5cg+5); cg>=4 -> (g,o) pairs ---
    {
        const int half = cg >> 2;             // 0: rows 0/20,  1: rows 40/60
        const int j0   = 5 * (cg & 3);
        const int rb   = half * 40;           // base row of first gate in pair

        u64 acc0[4][5], acc1[4][5];
#pragma unroll
        for (int q = 0; q < 4; q++)
#pragma unroll
            for (int p = 0; p < 5; p++) { acc0[q][p] = 0ull; acc1[q][p] = 0ull; }

#pragma unroll 2
        for (int kp = 0; kp < J_ / 2; kp++) {
            const int k = kp * 2;
            u64 fr[4], w0[5], w1r[5];
#pragma unroll
            for (int q = 0; q < 4; q++)
                fr[q] = *reinterpret_cast<const u64*>(&sm.x[rg + 16 * q][k]);
#pragma unroll
            for (int p = 0; p < 5; p++) {
                w0[p]  = *reinterpret_cast<const u64*>(&sm.wih[rb + j0 + p][k]);
                w1r[p] = *reinterpret_cast<const u64*>(&sm.wih[rb + 20 + j0 + p][k]);
            }
#pragma unroll
            for (int q = 0; q < 4; q++)
#pragma unroll
                for (int p = 0; p < 5; p++) {
                    fma2(acc0[q][p], fr[q], w0[p]);
                    fma2(acc1[q][p], fr[q], w1r[p]);
                }
        }

#pragma unroll
        for (int q = 0; q < 4; q++) {
            const int r = rg + 16 * q;
            float* op = g_gx + ((size_t)(bb + r) * S_ + s) * G_ + half * 40;
#pragma unroll
            for (int p = 0; p < 5; p++) {
                float l0, h0v, l1, h1v;
                upk2(acc0[q][p], l0, h0v);
                upk2(acc1[q][p], l1, h1v);
                float v0 = l0 + h0v + sm.b2v[rb + j0 + p];
                float v1 = l1 + h1v + sm.b2v[rb + 20 + j0 + p];
                *reinterpret_cast<u64*>(op + 2 * (j0 + p)) = pk2(v0, v1);
            }
        }
    }
}

// ---------------- LSTM recurrence: one warp = 4 batch elements ----------------
// Lane j<20 owns h[j],c[j] for 4 batches. Weights k-pair packed, pre-scaled by
// log2e (g rows 2*log2e) so every activation is a bare ex2.approx.
// h broadcast through smem: 1 STS + 5 LDS.128 per batch-step.
// Shared rcp: (sig i, sig f) and (tanh g, sig o) each use one rcp.

__global__ __launch_bounds__(32, 1) void lstm_kernel(
    const float* __restrict__ Whh, const float* __restrict__ Wf,
    const float* __restrict__ bf, const float* __restrict__ h0,
    const float* __restrict__ c0, float* __restrict__ out)
{
    __shared__ __align__(16) float hsh[4][32];

    const int lane = threadIdx.x;
    const int j    = (lane < H_) ? lane : 0;
    const int qb   = blockIdx.x * 4;   // batches qb..qb+3

    // weights, k-pair packed + prescaled
    u64 wi[10], wf_[10], wg[10], wo[10];
#pragma unroll
    for (int m = 0; m < 10; m++) {
        wi[m]  = pk2(Whh[(0 * H_ + j) * H_ + 2 * m] * L2E,
                     Whh[(0 * H_ + j) * H_ + 2 * m + 1] * L2E);
        wf_[m] = pk2(Whh[(1 * H_ + j) * H_ + 2 * m] * L2E,
                     Whh[(1 * H_ + j) * H_ + 2 * m + 1] * L2E);
        wg[m]  = pk2(Whh[(2 * H_ + j) * H_ + 2 * m] * (2.f * L2E),
                     Whh[(2 * H_ + j) * H_ + 2 * m + 1] * (2.f * L2E));
        wo[m]  = pk2(Whh[(3 * H_ + j) * H_ + 2 * m] * L2E,
                     Whh[(3 * H_ + j) * H_ + 2 * m + 1] * L2E);
    }

    float h[4], c[4], hs[4];
    const float* gp[4];
#pragma unroll
    for (int b = 0; b < 4; b++) {
        h[b]  = h0[(qb + b) * H_ + j];
        c[b]  = c0[(qb + b) * H_ + j];
        hs[b] = 0.f;
        gp[b] = g_gx + (size_t)(qb + b) * S_ * G_;
    }
    const int oIF = 2 * j;
    const int oGO = 40 + 2 * j;

    // prefetch ring: slot u holds step s+u
    u64 bif[4][2], bgo[4][2];
#pragma unroll
    for (int b = 0; b < 4; b++)
#pragma unroll
        for (int u = 0; u < 2; u++) {
            bif[b][u] = *reinterpret_cast<const u64*>(gp[b] + u * G_ + oIF);
            bgo[b][u] = *reinterpret_cast<const u64*>(gp[b] + u * G_ + oGO);
        }

    for (int s = 0; s < S_; s += 2) {
#pragma unroll
        for (int u = 0; u < 2; u++) {
            // publish current h's
#pragma unroll
            for (int b = 0; b < 4; b++) hsh[b][lane] = h[b];
            __syncwarp();

            const bool pf = (s + 2 + u) < S_;
#pragma unroll
            for (int b = 0; b < 4; b++) {
                // broadcast h as k-pairs (conflict-free smem broadcast)
                u64 hp[10];
#pragma unroll
                for (int m4 = 0; m4 < 5; m4++) {
                    ulonglong2 t = *reinterpret_cast<const ulonglong2*>(&hsh[b][4 * m4]);
                    hp[2 * m4]     = t.x;
                    hp[2 * m4 + 1] = t.y;
                }
                u64 ai = 0ull, af = 0ull, ag = 0ull, ao = 0ull;
#pragma unroll
                for (int m = 0; m < 10; m++) {
                    fma2(ai, wi[m],  hp[m]);
                    fma2(af, wf_[m], hp[m]);
                    fma2(ag, wg[m],  hp[m]);
                    fma2(ao, wo[m],  hp[m]);
                }
                float gi, gf, gg, go;
                upk2(bif[b][u], gi, gf);
                upk2(bgo[b][u], gg, go);
                // prefetch step s+2+u into this slot
                if (pf) {
                    bif[b][u] = *reinterpret_cast<const u64*>(gp[b] + (2 + u) * G_ + oIF);
                    bgo[b][u] = *reinterpret_cast<const u64*>(gp[b] + (2 + u) * G_ + oGO);
                }
                float e0, e1;
                upk2(ai, e0, e1); float vi = e0 + e1 + gi;
                upk2(af, e0, e1); float vf = e0 + e1 + gf;
                upk2(ag, e0, e1); float vg = e0 + e1 + gg;
                upk2(ao, e0, e1); float vo = e0 + e1 + go;
                // activations (args already in log2 domain)
                float Ei = ex2f(vi), Ef = ex2f(vf), Eg = ex2f(vg), Eo = ex2f(vo);
                float t1 = 1.f + Ei, t2 = 1.f + Ef;
                float R1 = rcpf(t1 * t2);
                float si = Ei * t2 * R1;
                float sf = Ef * t1 * R1;
                float t3 = Eg + 1.f, t4 = Eo + 1.f, t5 = Eg - 1.f;
                float R2 = rcpf(t3 * t4);
                float tg = t5 * t4 * R2;
                float so = Eo * t3 * R2;
                c[b] = fmaf(sf, c[b], si * tg);
                float Ec = ex2f(c[b] * (2.f * L2E));
                float tc = fmaf(-2.f, rcpf(Ec + 1.f), 1.f);
                h[b] = so * tc;
                hs[b] += h[b];
            }
            __syncwarp();
        }
#pragma unroll
        for (int b = 0; b < 4; b++) gp[b] += 2 * G_;
    }

    // y = Wf @ (hsum / S) + bf (mean commutes with the linear layer)
    float wa = (lane < H_) ? Wf[lane] : 0.f;
    float wb = (lane < H_) ? Wf[H_ + lane] : 0.f;
#pragma unroll
    for (int b = 0; b < 4; b++) {
        float y0 = wa * hs[b];
        float y1 = wb * hs[b];
#pragma unroll
        for (int off = 16; off; off >>= 1) {
            y0 += __shfl_xor_sync(0xffffffffu, y0, off);
            y1 += __shfl_xor_sync(0xffffffffu, y1, off);
        }
        if (lane == 0) {
            out[2 * (qb + b) + 0] = y0 * (1.f / S_) + bf[0];
            out[2 * (qb + b) + 1] = y1 * (1.f / S_) + bf[1];
        }
    }
}

// ---------------- launch ----------------
extern "C" void kernel_launch(void* const* d_in, const int* in_sizes, int n_in,
                              void* d_out, int out_size)
{
    const float* feed = (const float*)d_in[0];
    const float* W1   = (const float*)d_in[1];
    const float* b1   = (const float*)d_in[2];
    const float* Wih  = (const float*)d_in[3];
    const float* Whh  = (const float*)d_in[4];
    const float* bih  = (const float*)d_in[5];
    const float* bhh  = (const float*)d_in[6];
    const float* Wf   = (const float*)d_in[7];
    const float* bf   = (const float*)d_in[8];
    const float* h0   = (const float*)d_in[9];
    const float* c0   = (const float*)d_in[10];
    float* out = (float*)d_out;

    cudaFuncSetAttribute(gemm_kernel, cudaFuncAttributeMaxDynamicSharedMemorySize,
                         (int)sizeof(SmemG));
    gemm_kernel<<<(S_ * B_) / TILE_R, 128, sizeof(SmemG)>>>(feed, W1, b1, Wih, bih, bhh);
    lstm_kernel<<<B_ / 4, 32>>>(Whh, Wf, bf, h0, c0, out);
}

// round 6
// speedup vs baseline: 1.0179x; 1.0179x over previous
#include <cuda_runtime.h>

// Problem constants
#define B_  256
#define S_  2048
#define I_  128
#define J_  40    // LSTM_IN
#define G_  80    // 4*H
#define H_  20

typedef unsigned long long u64;

#define L2E 1.4426950408889634f   // log2(e)

// Scratch gx layout per (b,s): 80 floats, PRE-SCALED by log2e (gate g rows by 2*log2e):
//   float 2j   = gate i, row j      float 2j+1  = gate f, row j
//   float 40+2j = gate g, row j     float 41+2j = gate o, row j
__device__ __align__(256) float g_gx[(size_t)S_ * B_ * G_];

// ---------------- helpers ----------------
__device__ __forceinline__ u64 pk2(float lo, float hi) {
    u64 r;
    asm("mov.b64 %0, {%1, %2};" : "=l"(r) : "f"(lo), "f"(hi));
    return r;
}
__device__ __forceinline__ void upk2(u64 v, float& lo, float& hi) {
    asm("mov.b64 {%0, %1}, %2;" : "=f"(lo), "=f"(hi) : "l"(v));
}
__device__ __forceinline__ void fma2(u64& d, u64 a, u64 b) {
    asm("fma.rn.f32x2 %0, %1, %2, %0;" : "+l"(d) : "l"(a), "l"(b));
}
__device__ __forceinline__ float ex2f(float x) {
    float r;
    asm("ex2.approx.f32 %0, %1;" : "=f"(r) : "f"(x));
    return r;
}
__device__ __forceinline__ float rcpf(float x) {
    float r;
    asm("rcp.approx.f32 %0, %1;" : "=f"(r) : "f"(x));
    return r;
}

// ---------------- GEMM kernel ----------------
// gx = relu(feed@W1^T + b1) @ Wih^T + (bih+bhh), scaled by log2e (2*log2e for gate g),
// written pair-permuted, batch-major. 64-row tiles, 128 threads, 2 blocks/SM.

#define TILE_R 64

struct SmemG {
    float feed[TILE_R][I_ + 4];  // stride 132 words
    float x[TILE_R][J_ + 4];     // stride 44
    float w1[J_][I_ + 4];        // stride 132
    float wih[G_][J_ + 2];       // stride 42
    float b1v[J_];
    float b2v[G_];
};

__global__ __launch_bounds__(128, 2) void gemm_kernel(
    const float* __restrict__ feed, const float* __restrict__ W1,
    const float* __restrict__ b1, const float* __restrict__ Wih,
    const float* __restrict__ bih, const float* __restrict__ bhh)
{
    extern __shared__ char smem_raw[];
    SmemG& sm = *reinterpret_cast<SmemG*>(smem_raw);
    const int tid  = threadIdx.x;
    const int tile = blockIdx.x;           // 8192 tiles
    const int s    = tile >> 2;            // 4 tiles per timestep
    const int bb   = (tile & 3) * 64;      // batch base

    // --- stage weights/biases (gate scale folded into wih & b2v) ---
    for (int idx = tid; idx < J_ * I_; idx += 128)
        sm.w1[idx / I_][idx % I_] = W1[idx];
    for (int idx = tid; idx < G_ * J_; idx += 128) {
        int row = idx / J_;
        float sc = (row >= 40 && row < 60) ? (2.f * L2E) : L2E;
        sm.wih[row][idx % J_] = Wih[idx] * sc;
    }
    if (tid < J_) sm.b1v[tid] = b1[tid];
    if (tid < G_) {
        float sc = (tid >= 40 && tid < 60) ? (2.f * L2E) : L2E;
        sm.b2v[tid] = (bih[tid] + bhh[tid]) * sc;
    }

    // --- stage feed tile (float4, coalesced) ---
    for (int idx = tid; idx < TILE_R * (I_ / 4); idx += 128) {
        int r  = idx >> 5;
        int c4 = idx & 31;
        float4 v = *reinterpret_cast<const float4*>(
            feed + ((size_t)(bb + r) * S_ + s) * I_ + c4 * 4);
        *reinterpret_cast<float4*>(&sm.feed[r][c4 * 4]) = v;
    }
    __syncthreads();

    const int cg = tid & 7;   // 8 col groups
    const int rg = tid >> 3;  // 16 row groups; rows rg + 16q

    // --- phase 1: x[r][j], j0 = cg*5 ---
    {
        const int j0 = cg * 5;
        u64 acc[4][5];
#pragma unroll
        for (int q = 0; q < 4; q++)
#pragma unroll
            for (int p = 0; p < 5; p++) acc[q][p] = 0ull;

#pragma unroll 2
        for (int k4 = 0; k4 < I_ / 4; k4++) {
            const int k = k4 * 4;
            ulonglong2 fr[4], wj[5];
#pragma unroll
            for (int q = 0; q < 4; q++)
                fr[q] = *reinterpret_cast<const ulonglong2*>(&sm.feed[rg + 16 * q][k]);
#pragma unroll
            for (int p = 0; p < 5; p++)
                wj[p] = *reinterpret_cast<const ulonglong2*>(&sm.w1[j0 + p][k]);
#pragma unroll
            for (int q = 0; q < 4; q++)
#pragma unroll
                for (int p = 0; p < 5; p++) {
                    fma2(acc[q][p], fr[q].x, wj[p].x);
                    fma2(acc[q][p], fr[q].y, wj[p].y);
                }
        }
#pragma unroll
        for (int q = 0; q < 4; q++)
#pragma unroll
            for (int p = 0; p < 5; p++) {
                float lo, hi;
                upk2(acc[q][p], lo, hi);
                float v = lo + hi + sm.b1v[j0 + p];
                sm.x[rg + 16 * q][j0 + p] = fmaxf(v, 0.f);
            }
    }
    __syncthreads();

    // --- phase 2: cg<4 -> (i,f) pairs for j in [5cg,5cg+5); cg>=4 -> (g,o) pairs ---
    {
        const int half = cg >> 2;             // 0: rows 0/20,  1: rows 40/60
        const int j0   = 5 * (cg & 3);
        const int rb   = half * 40;           // base row of first gate in pair

        u64 acc0[4][5], acc1[4][5];
#pragma unroll
        for (int q = 0; q < 4; q++)
#pragma unroll
            for (int p = 0; p < 5; p++) { acc0[q][p] = 0ull; acc1[q][p] = 0ull; }

#pragma unroll 2
        for (int kp = 0; kp < J_ / 2; kp++) {
            const int k = kp * 2;
            u64 fr[4], w0[5], w1r[5];
#pragma unroll
            for (int q = 0; q < 4; q++)
                fr[q] = *reinterpret_cast<const u64*>(&sm.x[rg + 16 * q][k]);
#pragma unroll
            for (int p = 0; p < 5; p++) {
                w0[p]  = *reinterpret_cast<const u64*>(&sm.wih[rb + j0 + p][k]);
                w1r[p] = *reinterpret_cast<const u64*>(&sm.wih[rb + 20 + j0 + p][k]);
            }
#pragma unroll
            for (int q = 0; q < 4; q++)
#pragma unroll
                for (int p = 0; p < 5; p++) {
                    fma2(acc0[q][p], fr[q], w0[p]);
                    fma2(acc1[q][p], fr[q], w1r[p]);
                }
        }

#pragma unroll
        for (int q = 0; q < 4; q++) {
            const int r = rg + 16 * q;
            float* op = g_gx + ((size_t)(bb + r) * S_ + s) * G_ + half * 40;
#pragma unroll
            for (int p = 0; p < 5; p++) {
                float l0, h0v, l1, h1v;
                upk2(acc0[q][p], l0, h0v);
                upk2(acc1[q][p], l1, h1v);
                float v0 = l0 + h0v + sm.b2v[rb + j0 + p];
                float v1 = l1 + h1v + sm.b2v[rb + 20 + j0 + p];
                *reinterpret_cast<u64*>(op + 2 * (j0 + p)) = pk2(v0, v1);
            }
        }
    }
}

// ---------------- LSTM recurrence: one warp = 4 batch elements ----------------
// Lane j<20 owns h[j],c[j] for 4 batches. Weights k-pair packed, pre-scaled by
// log2e (g rows 2*log2e) so every activation is a bare ex2.approx.
// h broadcast through smem: 1 STS + 5 LDS.128 per batch-step.
// Shared rcp: (sig i, sig f) and (tanh g, sig o) each use one rcp.

__global__ __launch_bounds__(32, 1) void lstm_kernel(
    const float* __restrict__ Whh, const float* __restrict__ Wf,
    const float* __restrict__ bf, const float* __restrict__ h0,
    const float* __restrict__ c0, float* __restrict__ out)
{
    __shared__ __align__(16) float hsh[4][32];

    const int lane = threadIdx.x;
    const int j    = (lane < H_) ? lane : 0;
    const int qb   = blockIdx.x * 4;   // batches qb..qb+3

    // weights, k-pair packed + prescaled
    u64 wi[10], wf_[10], wg[10], wo[10];
#pragma unroll
    for (int m = 0; m < 10; m++) {
        wi[m]  = pk2(Whh[(0 * H_ + j) * H_ + 2 * m] * L2E,
                     Whh[(0 * H_ + j) * H_ + 2 * m + 1] * L2E);
        wf_[m] = pk2(Whh[(1 * H_ + j) * H_ + 2 * m] * L2E,
                     Whh[(1 * H_ + j) * H_ + 2 * m + 1] * L2E);
        wg[m]  = pk2(Whh[(2 * H_ + j) * H_ + 2 * m] * (2.f * L2E),
                     Whh[(2 * H_ + j) * H_ + 2 * m + 1] * (2.f * L2E));
        wo[m]  = pk2(Whh[(3 * H_ + j) * H_ + 2 * m] * L2E,
                     Whh[(3 * H_ + j) * H_ + 2 * m + 1] * L2E);
    }

    float h[4], c[4], hs[4];
    const float* gp[4];
#pragma unroll
    for (int b = 0; b < 4; b++) {
        h[b]  = h0[(qb + b) * H_ + j];
        c[b]  = c0[(qb + b) * H_ + j];
        hs[b] = 0.f;
        gp[b] = g_gx + (size_t)(qb + b) * S_ * G_;
    }
    const int oIF = 2 * j;
    const int oGO = 40 + 2 * j;

    // prefetch ring: slot u holds step s+u
    u64 bif[4][2], bgo[4][2];
#pragma unroll
    for (int b = 0; b < 4; b++)
#pragma unroll
        for (int u = 0; u < 2; u++) {
            bif[b][u] = *reinterpret_cast<const u64*>(gp[b] + u * G_ + oIF);
            bgo[b][u] = *reinterpret_cast<const u64*>(gp[b] + u * G_ + oGO);
        }

    for (int s = 0; s < S_; s += 2) {
#pragma unroll
        for (int u = 0; u < 2; u++) {
            // publish current h's
#pragma unroll
            for (int b = 0; b < 4; b++) hsh[b][lane] = h[b];
            __syncwarp();

            const bool pf = (s + 2 + u) < S_;
#pragma unroll
            for (int b = 0; b < 4; b++) {
                // broadcast h as k-pairs (conflict-free smem broadcast)
                u64 hp[10];
#pragma unroll
                for (int m4 = 0; m4 < 5; m4++) {
                    ulonglong2 t = *reinterpret_cast<const ulonglong2*>(&hsh[b][4 * m4]);
                    hp[2 * m4]     = t.x;
                    hp[2 * m4 + 1] = t.y;
                }
                u64 ai = 0ull, af = 0ull, ag = 0ull, ao = 0ull;
#pragma unroll
                for (int m = 0; m < 10; m++) {
                    fma2(ai, wi[m],  hp[m]);
                    fma2(af, wf_[m], hp[m]);
                    fma2(ag, wg[m],  hp[m]);
                    fma2(ao, wo[m],  hp[m]);
                }
                float gi, gf, gg, go;
                upk2(bif[b][u], gi, gf);
                upk2(bgo[b][u], gg, go);
                // prefetch step s+2+u into this slot
                if (pf) {
                    bif[b][u] = *reinterpret_cast<const u64*>(gp[b] + (2 + u) * G_ + oIF);
                    bgo[b][u] = *reinterpret_cast<const u64*>(gp[b] + (2 + u) * G_ + oGO);
                }
                float e0, e1;
                upk2(ai, e0, e1); float vi = e0 + e1 + gi;
                upk2(af, e0, e1); float vf = e0 + e1 + gf;
                upk2(ag, e0, e1); float vg = e0 + e1 + gg;
                upk2(ao, e0, e1); float vo = e0 + e1 + go;
                // activations (args already in log2 domain)
                float Ei = ex2f(vi), Ef = ex2f(vf), Eg = ex2f(vg), Eo = ex2f(vo);
                float t1 = 1.f + Ei, t2 = 1.f + Ef;
                float R1 = rcpf(t1 * t2);
                float si = Ei * t2 * R1;
                float sf = Ef * t1 * R1;
                float t3 = Eg + 1.f, t4 = Eo + 1.f, t5 = Eg - 1.f;
                float R2 = rcpf(t3 * t4);
                float tg = t5 * t4 * R2;
                float so = Eo * t3 * R2;
                c[b] = fmaf(sf, c[b], si * tg);
                float Ec = ex2f(c[b] * (2.f * L2E));
                float tc = fmaf(-2.f, rcpf(Ec + 1.f), 1.f);
                h[b] = so * tc;
                hs[b] += h[b];
            }
            __syncwarp();
        }
#pragma unroll
        for (int b = 0; b < 4; b++) gp[b] += 2 * G_;
    }

    // y = Wf @ (hsum / S) + bf (mean commutes with the linear layer)
    float wa = (lane < H_) ? Wf[lane] : 0.f;
    float wb = (lane < H_) ? Wf[H_ + lane] : 0.f;
#pragma unroll
    for (int b = 0; b < 4; b++) {
        float y0 = wa * hs[b];
        float y1 = wb * hs[b];
#pragma unroll
        for (int off = 16; off; off >>= 1) {
            y0 += __shfl_xor_sync(0xffffffffu, y0, off);
            y1 += __shfl_xor_sync(0xffffffffu, y1, off);
        }
        if (lane == 0) {
            out[2 * (qb + b) + 0] = y0 * (1.f / S_) + bf[0];
            out[2 * (qb + b) + 1] = y1 * (1.f / S_) + bf[1];
        }
    }
}

// ---------------- launch ----------------
extern "C" void kernel_launch(void* const* d_in, const int* in_sizes, int n_in,
                              void* d_out, int out_size)
{
    const float* feed = (const float*)d_in[0];
    const float* W1   = (const float*)d_in[1];
    const float* b1   = (const float*)d_in[2];
    const float* Wih  = (const float*)d_in[3];
    const float* Whh  = (const float*)d_in[4];
    const float* bih  = (const float*)d_in[5];
    const float* bhh  = (const float*)d_in[6];
    const float* Wf   = (const float*)d_in[7];
    const float* bf   = (const float*)d_in[8];
    const float* h0   = (const float*)d_in[9];
    const float* c0   = (const float*)d_in[10];
    float* out = (float*)d_out;

    cudaFuncSetAttribute(gemm_kernel, cudaFuncAttributeMaxDynamicSharedMemorySize,
                         (int)sizeof(SmemG));
    gemm_kernel<<<(S_ * B_) / TILE_R, 128, sizeof(SmemG)>>>(feed, W1, b1, Wih, bih, bhh);
    lstm_kernel<<<B_ / 4, 32>>>(Whh, Wf, bf, h0, c0, out);
}

// round 7
// speedup vs baseline: 1.5915x; 1.5636x over previous
#include <cuda_runtime.h>

// Problem constants
#define B_  256
#define S_  2048
#define I_  128
#define J_  40    // LSTM_IN
#define G_  80    // 4*H
#define H_  20

typedef unsigned long long u64;

#define L2E 1.4426950408889634f   // log2(e)

// Scratch gx layout per (b,s): 80 floats, PRE-SCALED by L2E (gate g rows by 2*L2E):
//   float 2j    = gate i, row j     float 2j+1  = gate f, row j
//   float 40+2j = gate g, row j     float 41+2j = gate o, row j
__device__ __align__(256) float g_gx[(size_t)S_ * B_ * G_];

// ---------------- helpers ----------------
__device__ __forceinline__ u64 pk2(float lo, float hi) {
    u64 r;
    asm("mov.b64 %0, {%1, %2};" : "=l"(r) : "f"(lo), "f"(hi));
    return r;
}
__device__ __forceinline__ void upk2(u64 v, float& lo, float& hi) {
    asm("mov.b64 {%0, %1}, %2;" : "=f"(lo), "=f"(hi) : "l"(v));
}
__device__ __forceinline__ void fma2(u64& d, u64 a, u64 b) {
    asm("fma.rn.f32x2 %0, %1, %2, %0;" : "+l"(d) : "l"(a), "l"(b));
}
__device__ __forceinline__ float ex2f(float x) {
    float r;
    asm("ex2.approx.f32 %0, %1;" : "=f"(r) : "f"(x));
    return r;
}
__device__ __forceinline__ float rcpf(float x) {
    float r;
    asm("rcp.approx.f32 %0, %1;" : "=f"(r) : "f"(x));
    return r;
}

// ---------------- GEMM kernel (R2 tiles, pair-permuted scaled epilogue) ----------------
// gx = relu(feed@W1^T + b1) @ Wih^T + (bih+bhh), scaled, pair-permuted, batch-major.
// 128-row tiles (fixed s), 256 threads. Thread rows {rg, rg+32, rg+64, rg+96}.

#define TILE_R 128

struct SmemG {
    float feed[TILE_R][I_ + 4];  // stride 132 words
    float x[TILE_R][J_ + 4];     // stride 44
    float w1[J_][I_ + 4];        // stride 132
    float wih[G_][J_ + 2];       // stride 42
    float b1v[J_];
    float b2v[G_];
};

__global__ __launch_bounds__(256, 1) void gemm_kernel(
    const float* __restrict__ feed, const float* __restrict__ W1,
    const float* __restrict__ b1, const float* __restrict__ Wih,
    const float* __restrict__ bih, const float* __restrict__ bhh)
{
    extern __shared__ char smem_raw[];
    SmemG& sm = *reinterpret_cast<SmemG*>(smem_raw);
    const int tid  = threadIdx.x;
    const int tile = blockIdx.x;           // 4096 tiles
    const int s    = tile >> 1;            // 2 tiles per timestep
    const int bb   = (tile & 1) * 128;     // batch base

    // --- stage weights/biases (activation scale folded into wih & b2v) ---
    for (int idx = tid; idx < J_ * I_; idx += 256)
        sm.w1[idx / I_][idx % I_] = W1[idx];
    for (int idx = tid; idx < G_ * J_; idx += 256) {
        int row = idx / J_;
        float sc = (row >= 40 && row < 60) ? (2.f * L2E) : L2E;
        sm.wih[row][idx % J_] = Wih[idx] * sc;
    }
    if (tid < J_) sm.b1v[tid] = b1[tid];
    if (tid < G_) {
        float sc = (tid >= 40 && tid < 60) ? (2.f * L2E) : L2E;
        sm.b2v[tid] = (bih[tid] + bhh[tid]) * sc;
    }

    // --- stage feed tile (float4, coalesced) ---
    for (int idx = tid; idx < TILE_R * (I_ / 4); idx += 256) {
        int r  = idx >> 5;
        int c4 = idx & 31;
        float4 v = *reinterpret_cast<const float4*>(
            feed + ((size_t)(bb + r) * S_ + s) * I_ + c4 * 4);
        *reinterpret_cast<float4*>(&sm.feed[r][c4 * 4]) = v;
    }
    __syncthreads();

    const int cg = tid & 7;   // 8 col groups
    const int rg = tid >> 3;  // 32 row groups; rows rg + 32q

    // --- phase 1: x[r][j], j0 = cg*5, LDS.128 k-quads ---
    {
        const int j0 = cg * 5;
        u64 acc[4][5];
#pragma unroll
        for (int q = 0; q < 4; q++)
#pragma unroll
            for (int p = 0; p < 5; p++) acc[q][p] = 0ull;

#pragma unroll 2
        for (int k4 = 0; k4 < I_ / 4; k4++) {
            const int k = k4 * 4;
            ulonglong2 fr[4], wj[5];
#pragma unroll
            for (int q = 0; q < 4; q++)
                fr[q] = *reinterpret_cast<const ulonglong2*>(&sm.feed[rg + 32 * q][k]);
#pragma unroll
            for (int p = 0; p < 5; p++)
                wj[p] = *reinterpret_cast<const ulonglong2*>(&sm.w1[j0 + p][k]);
#pragma unroll
            for (int q = 0; q < 4; q++)
#pragma unroll
                for (int p = 0; p < 5; p++) {
                    fma2(acc[q][p], fr[q].x, wj[p].x);
                    fma2(acc[q][p], fr[q].y, wj[p].y);
                }
        }
#pragma unroll
        for (int q = 0; q < 4; q++)
#pragma unroll
            for (int p = 0; p < 5; p++) {
                float lo, hi;
                upk2(acc[q][p], lo, hi);
                float v = lo + hi + sm.b1v[j0 + p];
                sm.x[rg + 32 * q][j0 + p] = fmaxf(v, 0.f);
            }
    }
    __syncthreads();

    // --- phase 2: cg<4 -> (i,f) pair rows; cg>=4 -> (g,o) pair rows; j0 = 5*(cg&3) ---
    {
        const int half = cg >> 2;             // 0: gate rows 0/20,  1: rows 40/60
        const int j0   = 5 * (cg & 3);
        const int rb   = half * 40;

        u64 acc0[4][5], acc1[4][5];
#pragma unroll
        for (int q = 0; q < 4; q++)
#pragma unroll
            for (int p = 0; p < 5; p++) { acc0[q][p] = 0ull; acc1[q][p] = 0ull; }

#pragma unroll 2
        for (int kp = 0; kp < J_ / 2; kp++) {
            const int k = kp * 2;
            u64 fr[4], w0[5], w1r[5];
#pragma unroll
            for (int q = 0; q < 4; q++)
                fr[q] = *reinterpret_cast<const u64*>(&sm.x[rg + 32 * q][k]);
#pragma unroll
            for (int p = 0; p < 5; p++) {
                w0[p]  = *reinterpret_cast<const u64*>(&sm.wih[rb + j0 + p][k]);
                w1r[p] = *reinterpret_cast<const u64*>(&sm.wih[rb + 20 + j0 + p][k]);
            }
#pragma unroll
            for (int q = 0; q < 4; q++)
#pragma unroll
                for (int p = 0; p < 5; p++) {
                    fma2(acc0[q][p], fr[q], w0[p]);
                    fma2(acc1[q][p], fr[q], w1r[p]);
                }
        }

#pragma unroll
        for (int q = 0; q < 4; q++) {
            const int r = rg + 32 * q;
            float* op = g_gx + ((size_t)(bb + r) * S_ + s) * G_ + half * 40;
#pragma unroll
            for (int p = 0; p < 5; p++) {
                float l0, h0v, l1, h1v;
                upk2(acc0[q][p], l0, h0v);
                upk2(acc1[q][p], l1, h1v);
                float v0 = l0 + h0v + sm.b2v[rb + j0 + p];
                float v1 = l1 + h1v + sm.b2v[rb + 20 + j0 + p];
                *reinterpret_cast<u64*>(op + 2 * (j0 + p)) = pk2(v0, v1);
            }
        }
    }
}

// ---------------- LSTM: one warp = 2 batches, fully interleaved chains ----------------
// Lane j<20 owns h[j],c[j] for both batches. Whh prescaled, k-pair packed per gate.
// Per step: shfl h-broadcast (A/B interleaved), 4 gate chains of depth 10 per batch
// (8 fma2 per k-pair, 2-batch ILP), shared-rcp activations (8 MUFU/batch-step).

__global__ __launch_bounds__(32, 1) void lstm_kernel(
    const float* __restrict__ Whh, const float* __restrict__ Wf,
    const float* __restrict__ bf, const float* __restrict__ h0,
    const float* __restrict__ c0, float* __restrict__ out)
{
    const int lane = threadIdx.x;
    const int j    = (lane < H_) ? lane : 0;
    const int b0   = blockIdx.x * 2, b1 = b0 + 1;

    // weights: per gate, k-pair packed + prescaled
    u64 wi[10], wf_[10], wg[10], wo[10];
#pragma unroll
    for (int m = 0; m < 10; m++) {
        wi[m]  = pk2(Whh[(0 * H_ + j) * H_ + 2 * m] * L2E,
                     Whh[(0 * H_ + j) * H_ + 2 * m + 1] * L2E);
        wf_[m] = pk2(Whh[(1 * H_ + j) * H_ + 2 * m] * L2E,
                     Whh[(1 * H_ + j) * H_ + 2 * m + 1] * L2E);
        wg[m]  = pk2(Whh[(2 * H_ + j) * H_ + 2 * m] * (2.f * L2E),
                     Whh[(2 * H_ + j) * H_ + 2 * m + 1] * (2.f * L2E));
        wo[m]  = pk2(Whh[(3 * H_ + j) * H_ + 2 * m] * L2E,
                     Whh[(3 * H_ + j) * H_ + 2 * m + 1] * L2E);
    }

    float hA = h0[b0 * H_ + j], cA = c0[b0 * H_ + j], sA = 0.f;
    float hB = h0[b1 * H_ + j], cB = c0[b1 * H_ + j], sB = 0.f;

    const float* gxA = g_gx + (size_t)b0 * S_ * G_;
    const float* gxB = g_gx + (size_t)b1 * S_ * G_;
    const int oIF = 2 * j;
    const int oGO = 40 + 2 * j;

    // prefetch ring: slot u holds step s+u (depth 4)
    u64 fifA[4], fgoA[4], fifB[4], fgoB[4];
#pragma unroll
    for (int u = 0; u < 4; u++) {
        fifA[u] = *reinterpret_cast<const u64*>(gxA + (size_t)u * G_ + oIF);
        fgoA[u] = *reinterpret_cast<const u64*>(gxA + (size_t)u * G_ + oGO);
        fifB[u] = *reinterpret_cast<const u64*>(gxB + (size_t)u * G_ + oIF);
        fgoB[u] = *reinterpret_cast<const u64*>(gxB + (size_t)u * G_ + oGO);
    }

    // one interleaved step for both batches
    auto step2 = [&](u64 gifA, u64 ggoA, u64 gifB, u64 ggoB) {
        // --- broadcast h as k-pairs, A/B interleaved ---
        u64 hpA[10], hpB[10];
#pragma unroll
        for (int m = 0; m < 10; m++) {
            float a0 = __shfl_sync(0xffffffffu, hA, 2 * m);
            float b0v = __shfl_sync(0xffffffffu, hB, 2 * m);
            float a1 = __shfl_sync(0xffffffffu, hA, 2 * m + 1);
            float b1v = __shfl_sync(0xffffffffu, hB, 2 * m + 1);
            hpA[m] = pk2(a0, a1);
            hpB[m] = pk2(b0v, b1v);
        }
        // --- 4 gate chains x depth 10, both batches interleaved ---
        u64 aiA = 0ull, afA = 0ull, agA = 0ull, aoA = 0ull;
        u64 aiB = 0ull, afB = 0ull, agB = 0ull, aoB = 0ull;
#pragma unroll
        for (int m = 0; m < 10; m++) {
            fma2(aiA, wi[m],  hpA[m]);  fma2(aiB, wi[m],  hpB[m]);
            fma2(afA, wf_[m], hpA[m]);  fma2(afB, wf_[m], hpB[m]);
            fma2(agA, wg[m],  hpA[m]);  fma2(agB, wg[m],  hpB[m]);
            fma2(aoA, wo[m],  hpA[m]);  fma2(aoB, wo[m],  hpB[m]);
        }
        // --- horizontal sums + gx add (prescaled by L2E / 2*L2E) ---
        float e0, e1, giA, gfA, ggA, goA, giB, gfB, ggB, goB;
        upk2(gifA, giA, gfA); upk2(ggoA, ggA, goA);
        upk2(gifB, giB, gfB); upk2(ggoB, ggB, goB);
        upk2(aiA, e0, e1); float viA = e0 + e1 + giA;
        upk2(aiB, e0, e1); float viB = e0 + e1 + giB;
        upk2(afA, e0, e1); float vfA = e0 + e1 + gfA;
        upk2(afB, e0, e1); float vfB = e0 + e1 + gfB;
        upk2(agA, e0, e1); float vgA = e0 + e1 + ggA;
        upk2(agB, e0, e1); float vgB = e0 + e1 + ggB;
        upk2(aoA, e0, e1); float voA = e0 + e1 + goA;
        upk2(aoB, e0, e1); float voB = e0 + e1 + goB;
        // --- activations (log2 domain), shared rcp per pair, A/B interleaved ---
        float EiA = ex2f(viA), EiB = ex2f(viB);
        float EfA = ex2f(vfA), EfB = ex2f(vfB);
        float EgA = ex2f(vgA), EgB = ex2f(vgB);
        float EoA = ex2f(voA), EoB = ex2f(voB);
        float t1A = 1.f + EiA, t2A = 1.f + EfA;
        float t1B = 1.f + EiB, t2B = 1.f + EfB;
        float R1A = rcpf(t1A * t2A), R1B = rcpf(t1B * t2B);
        float t3A = EgA + 1.f, t4A = EoA + 1.f, t5A = EgA - 1.f;
        float t3B = EgB + 1.f, t4B = EoB + 1.f, t5B = EgB - 1.f;
        float R2A = rcpf(t3A * t4A), R2B = rcpf(t3B * t4B);
        float siA = EiA * t2A * R1A, sfA = EfA * t1A * R1A;
        float siB = EiB * t2B * R1B, sfB = EfB * t1B * R1B;
        float tgA = t5A * t4A * R2A, soA = EoA * t3A * R2A;
        float tgB = t5B * t4B * R2B, soB = EoB * t3B * R2B;
        cA = fmaf(sfA, cA, siA * tgA);
        cB = fmaf(sfB, cB, siB * tgB);
        float EcA = ex2f(cA * (2.f * L2E)), EcB = ex2f(cB * (2.f * L2E));
        float tcA = fmaf(-2.f, rcpf(EcA + 1.f), 1.f);
        float tcB = fmaf(-2.f, rcpf(EcB + 1.f), 1.f);
        hA = soA * tcA;
        hB = soB * tcB;
        sA += hA;
        sB += hB;
    };

    for (int s = 0; s < S_; s += 4) {
#pragma unroll
        for (int u = 0; u < 4; u++) {
            u64 aIF = fifA[u], aGO = fgoA[u], bIF = fifB[u], bGO = fgoB[u];
            const int sp = s + 4 + u;
            if (sp < S_) {  // prefetch next occupant of this slot first
                fifA[u] = *reinterpret_cast<const u64*>(gxA + (size_t)sp * G_ + oIF);
                fgoA[u] = *reinterpret_cast<const u64*>(gxA + (size_t)sp * G_ + oGO);
                fifB[u] = *reinterpret_cast<const u64*>(gxB + (size_t)sp * G_ + oIF);
                fgoB[u] = *reinterpret_cast<const u64*>(gxB + (size_t)sp * G_ + oGO);
            }
            step2(aIF, aGO, bIF, bGO);
        }
    }

    // y = Wf @ (hsum / S) + bf (mean commutes with the linear layer)
    float wa = (lane < H_) ? Wf[lane] : 0.f;
    float wb = (lane < H_) ? Wf[H_ + lane] : 0.f;
    float y0A = wa * sA, y1A = wb * sA, y0B = wa * sB, y1B = wb * sB;
#pragma unroll
    for (int off = 16; off; off >>= 1) {
        y0A += __shfl_xor_sync(0xffffffffu, y0A, off);
        y1A += __shfl_xor_sync(0xffffffffu, y1A, off);
        y0B += __shfl_xor_sync(0xffffffffu, y0B, off);
        y1B += __shfl_xor_sync(0xffffffffu, y1B, off);
    }
    if (lane == 0) {
        out[2 * b0 + 0] = y0A * (1.f / S_) + bf[0];
        out[2 * b0 + 1] = y1A * (1.f / S_) + bf[1];
        out[2 * b1 + 0] = y0B * (1.f / S_) + bf[0];
        out[2 * b1 + 1] = y1B * (1.f / S_) + bf[1];
    }
}

// ---------------- launch ----------------
extern "C" void kernel_launch(void* const* d_in, const int* in_sizes, int n_in,
                              void* d_out, int out_size)
{
    const float* feed = (const float*)d_in[0];
    const float* W1   = (const float*)d_in[1];
    const float* b1   = (const float*)d_in[2];
    const float* Wih  = (const float*)d_in[3];
    const float* Whh  = (const float*)d_in[4];
    const float* bih  = (const float*)d_in[5];
    const float* bhh  = (const float*)d_in[6];
    const float* Wf   = (const float*)d_in[7];
    const float* bf   = (const float*)d_in[8];
    const float* h0   = (const float*)d_in[9];
    const float* c0   = (const float*)d_in[10];
    float* out = (float*)d_out;

    cudaFuncSetAttribute(gemm_kernel, cudaFuncAttributeMaxDynamicSharedMemorySize,
                         (int)sizeof(SmemG));
    gemm_kernel<<<(S_ * B_) / TILE_R, 256, sizeof(SmemG)>>>(feed, W1, b1, Wih, bih, bhh);
    lstm_kernel<<<B_ / 2, 32>>>(Whh, Wf, bf, h0, c0, out);
}